// round 1
// baseline (speedup 1.0000x reference)
#include <cuda_runtime.h>
#include <cstddef>

// Problem dims
#define B_    256
#define T_    100
#define IN_   128
#define H_    1024
#define OUT_  35
#define TB_   (B_ * T_)   // 25600 = rows of the big batched GEMMs

// ---------------- scratch (device globals; no allocation allowed) ----------
__device__ float g_xs[(size_t)TB_ * IN_];     // x transposed to [T,B,IN] and /15
__device__ float g_cur[(size_t)TB_ * H_];     // layer currents [T,B,H]
__device__ float g_cur4[(size_t)TB_ * OUT_];  // layer-4 currents [T,B,OUT]
__device__ float g_q1[H_ * IN_];
__device__ float g_q2[H_ * H_];
__device__ float g_q3[H_ * H_];
__device__ float g_q4[OUT_ * H_];

// ---------------- fake-quant (matches jnp: clip, round-half-even) ----------
__global__ void quant_kernel(const float* __restrict__ w, float* __restrict__ q,
                             int n, float wmin, float wmax, float scale) {
    int i = blockIdx.x * blockDim.x + threadIdx.x;
    if (i >= n) return;
    float wc = fminf(fmaxf(w[i], wmin), wmax);
    float t  = __fdiv_rn(__fsub_rn(wc, wmin), scale);
    // rintf = round-half-to-even, matching jnp.round
    q[i] = __fadd_rn(__fmul_rn(rintf(t), scale), wmin);
}

// ---------------- x: [B,T,IN] -> [T,B,IN], scaled by 1/15 ------------------
__global__ void prep_x_kernel(const float* __restrict__ x, float* __restrict__ xs) {
    int idx = blockIdx.x * blockDim.x + threadIdx.x;
    if (idx >= TB_ * IN_) return;
    int i  = idx % IN_;
    int rb = idx / IN_;        // = t*B + b
    int b  = rb % B_;
    int t  = rb / B_;
    xs[idx] = __fdiv_rn(x[((size_t)b * T_ + t) * IN_ + i], 15.0f);
}

// ---------------- tiled SGEMM: C[M,N] = A[M,K] @ W[N,K]^T ------------------
// A row-major (lda=K), W row-major (ldw=K)  => both contiguous along K ("NT").
// 128x128 block tile, BK=16, 256 threads, 8x8 per-thread micro-tile.
#define BM 128
#define BN 128
#define BK 16

__global__ __launch_bounds__(256)
void gemm_nt_kernel(const float* __restrict__ A, const float* __restrict__ W,
                    float* __restrict__ C, int M, int N, int K) {
    __shared__ float As[BK][BM];
    __shared__ float Ws[BK][BN];

    const int tid  = threadIdx.x;
    const int tr   = tid >> 4;   // 0..15 (row group)
    const int tc   = tid & 15;   // 0..15 (col group)
    const int row0 = blockIdx.y * BM;
    const int col0 = blockIdx.x * BN;

    float acc[8][8];
#pragma unroll
    for (int i = 0; i < 8; i++)
#pragma unroll
        for (int j = 0; j < 8; j++) acc[i][j] = 0.0f;

    for (int k0 = 0; k0 < K; k0 += BK) {
        // ---- load A tile 128x16 (512 float4, 2 per thread), M,K tile-exact
#pragma unroll
        for (int l = 0; l < 2; l++) {
            int lin = tid + l * 256;
            int r   = lin >> 2;
            int c4  = (lin & 3) << 2;
            float4 v = *(const float4*)&A[(size_t)(row0 + r) * K + k0 + c4];
            As[c4 + 0][r] = v.x;
            As[c4 + 1][r] = v.y;
            As[c4 + 2][r] = v.z;
            As[c4 + 3][r] = v.w;
        }
        // ---- load W tile 128x16, guard rows (N=35 case)
#pragma unroll
        for (int l = 0; l < 2; l++) {
            int lin = tid + l * 256;
            int r   = lin >> 2;
            int c4  = (lin & 3) << 2;
            int wr  = col0 + r;
            float4 v = make_float4(0.f, 0.f, 0.f, 0.f);
            if (wr < N) v = *(const float4*)&W[(size_t)wr * K + k0 + c4];
            Ws[c4 + 0][r] = v.x;
            Ws[c4 + 1][r] = v.y;
            Ws[c4 + 2][r] = v.z;
            Ws[c4 + 3][r] = v.w;
        }
        __syncthreads();

#pragma unroll
        for (int k = 0; k < BK; k++) {
            float4 a0 = *(const float4*)&As[k][tr * 8];
            float4 a1 = *(const float4*)&As[k][tr * 8 + 4];
            float4 b0 = *(const float4*)&Ws[k][tc * 8];
            float4 b1 = *(const float4*)&Ws[k][tc * 8 + 4];
            float a[8] = {a0.x, a0.y, a0.z, a0.w, a1.x, a1.y, a1.z, a1.w};
            float b[8] = {b0.x, b0.y, b0.z, b0.w, b1.x, b1.y, b1.z, b1.w};
#pragma unroll
            for (int i = 0; i < 8; i++)
#pragma unroll
                for (int j = 0; j < 8; j++)
                    acc[i][j] = fmaf(a[i], b[j], acc[i][j]);
        }
        __syncthreads();
    }

#pragma unroll
    for (int i = 0; i < 8; i++) {
        int row = row0 + tr * 8 + i;
        if (row >= M) continue;
#pragma unroll
        for (int j = 0; j < 8; j++) {
            int col = col0 + tc * 8 + j;
            if (col < N) C[(size_t)row * N + col] = acc[i][j];
        }
    }
}

// ---------------- LIF scans (reset_delay semantics, thr=1) -----------------
// subtract-reset: reset from PREVIOUS mem; base = beta*m + cur; m = base - reset
__global__ void lif_sub_kernel(const float* __restrict__ cur, float* __restrict__ spk,
                               float beta, int n) {
    int idx = blockIdx.x * blockDim.x + threadIdx.x;
    if (idx >= n) return;
    float m = 0.0f;
    for (int t = 0; t < T_; t++) {
        float c     = cur[(size_t)t * n + idx];
        float reset = (m > 1.0f) ? 1.0f : 0.0f;
        float base  = __fadd_rn(__fmul_rn(beta, m), c);
        m = base - reset;                       // thr = 1
        spk[(size_t)t * n + idx] = (m > 1.0f) ? 1.0f : 0.0f;
    }
}

// zero-reset (layer 4): m = base*(1-reset); outputs spk4 AND mem4
__global__ void lif_zero_kernel(const float* __restrict__ cur, float* __restrict__ spk,
                                float* __restrict__ mem, float beta, int n) {
    int idx = blockIdx.x * blockDim.x + threadIdx.x;
    if (idx >= n) return;
    float m = 0.0f;
    for (int t = 0; t < T_; t++) {
        float c    = cur[(size_t)t * n + idx];
        bool  rst  = (m > 1.0f);
        float base = __fadd_rn(__fmul_rn(beta, m), c);
        m = rst ? 0.0f : base;
        spk[(size_t)t * n + idx] = (m > 1.0f) ? 1.0f : 0.0f;
        mem[(size_t)t * n + idx] = m;
    }
}

// ---------------------------------------------------------------------------
extern "C" void kernel_launch(void* const* d_in, const int* in_sizes, int n_in,
                              void* d_out, int out_size) {
    const float* x  = (const float*)d_in[0];
    const float* w1 = (const float*)d_in[1];
    const float* w2 = (const float*)d_in[2];
    const float* w3 = (const float*)d_in[3];
    const float* w4 = (const float*)d_in[4];
    float* out = (float*)d_out;

    float *xs, *cur, *cur4, *q1, *q2, *q3, *q4;
    cudaGetSymbolAddress((void**)&xs,   g_xs);
    cudaGetSymbolAddress((void**)&cur,  g_cur);
    cudaGetSymbolAddress((void**)&cur4, g_cur4);
    cudaGetSymbolAddress((void**)&q1,   g_q1);
    cudaGetSymbolAddress((void**)&q2,   g_q2);
    cudaGetSymbolAddress((void**)&q3,   g_q3);
    cudaGetSymbolAddress((void**)&q4,   g_q4);

    const size_t SPK  = (size_t)TB_ * H_;    // 26,214,400
    const size_t SPK4 = (size_t)TB_ * OUT_;  //    896,000
    float* spk1 = out;
    float* spk2 = out + SPK;
    float* spk3 = out + 2 * SPK;
    float* spk4 = out + 3 * SPK;
    float* mem4 = out + 3 * SPK + SPK4;

    // scales exactly as Python computes them (double, then used at f32)
    const float scale1 = (float)((0.5 - (-0.5)) / 15.0);
    const float scale2 = (float)((1.0 - 0.001) / 15.0);

    // ---- weight fake-quantization (hoisted out of time loop, as reference)
    quant_kernel<<<(H_ * IN_ + 255) / 256, 256>>>(w1, q1, H_ * IN_, -0.5f, 0.5f, scale1);
    quant_kernel<<<(H_ * H_  + 255) / 256, 256>>>(w2, q2, H_ * H_,  0.001f, 1.0f, scale2);
    quant_kernel<<<(H_ * H_  + 255) / 256, 256>>>(w3, q3, H_ * H_,  0.001f, 1.0f, scale2);
    quant_kernel<<<(OUT_ * H_ + 255) / 256, 256>>>(w4, q4, OUT_ * H_, 0.001f, 1.0f, scale2);

    // ---- x -> [T,B,IN] / 15
    prep_x_kernel<<<(TB_ * IN_ + 255) / 256, 256>>>(x, xs);

    dim3 blk(256);
    dim3 gHid(H_ / BN, TB_ / BM);   // (8, 200)
    dim3 gOut(1, TB_ / BM);         // (1, 200)  N=35 fits one column tile

    // Layer 1: cur = xs @ q1^T ; LIF(beta=0.9, subtract) -> spk1 (output!)
    gemm_nt_kernel<<<gHid, blk>>>(xs, q1, cur, TB_, H_, IN_);
    lif_sub_kernel<<<(B_ * H_ + 255) / 256, 256>>>(cur, spk1, 0.9f, B_ * H_);

    // Layer 2: cur = spk1 @ q2^T ; LIF(0.85, subtract) -> spk2
    gemm_nt_kernel<<<gHid, blk>>>(spk1, q2, cur, TB_, H_, H_);
    lif_sub_kernel<<<(B_ * H_ + 255) / 256, 256>>>(cur, spk2, 0.85f, B_ * H_);

    // Layer 3: cur = spk2 @ q3^T ; LIF(0.8, subtract) -> spk3
    gemm_nt_kernel<<<gHid, blk>>>(spk2, q3, cur, TB_, H_, H_);
    lif_sub_kernel<<<(B_ * H_ + 255) / 256, 256>>>(cur, spk3, 0.8f, B_ * H_);

    // Layer 4: cur4 = spk3 @ q4^T ; LIF(0.95, zero) -> spk4, mem4
    gemm_nt_kernel<<<gOut, blk>>>(spk3, q4, cur4, TB_, OUT_, H_);
    lif_zero_kernel<<<(B_ * OUT_ + 255) / 256, 256>>>(cur4, spk4, mem4, 0.95f, B_ * OUT_);

    (void)in_sizes; (void)n_in; (void)out_size;
}